// round 1
// baseline (speedup 1.0000x reference)
#include <cuda_runtime.h>

// ---------------------------------------------------------------------------
// CustomSTFT collapses algebraically:
//   mag/phase roundtrip == identity  (rr=sr, ri=si)
//   iDFT(DFT(win*frame)) == (N/2)/FREQ * win*frame   (exact real-DFT pair)
//   overlap-add  =>  out[b,n] = x[b,n] * W[n]
// where W[n] = (400/401) * sum of up-to-4 overlapping hann window values.
// So the kernel is a pointwise multiply by a precomputed 480000-float vector.
// ---------------------------------------------------------------------------

#define NFFT   800
#define HOP    200
#define FREQN  401          // N_FFT/2 + 1
#define PADW   400
#define TLEN   480000
#define NBATCH 32
#define FRAMES 2401         // (480800 - 800)/200 + 1

__device__ float g_win[NFFT];
__device__ float g_w[TLEN];

// Kernel 1: hann window, computed in double to bit-match np.hanning cast to f32.
__global__ void k_win() {
    int w = blockIdx.x * blockDim.x + threadIdx.x;
    if (w < NFFT) {
        double v = 0.5 - 0.5 * cos(2.0 * 3.14159265358979323846 * (double)w / (double)(NFFT - 1));
        g_win[w] = (float)v;
    }
}

// Kernel 2: per-position overlap-add window weight, incl. the (N/2)/FREQ scale.
__global__ void k_wfull() {
    int n = blockIdx.x * blockDim.x + threadIdx.x;
    if (n >= TLEN) return;
    int p = n + PADW;           // position in padded signal
    int q = p / HOP;            // last frame index touching p (before validity)
    int r = p % HOP;
    double s = 0.0;
#pragma unroll
    for (int j = 0; j < 4; j++) {
        int t = q - j;          // frame index contributing win[r + HOP*j]
        if (t >= 0 && t < FRAMES) s += (double)g_win[r + HOP * j];
    }
    g_w[n] = (float)(s * ((double)(NFFT / 2) / (double)FREQN));
}

// Kernel 3: streaming elementwise multiply, float4-vectorized.
// Total float4s: 32*480000/4 = 3,840,000.  Per-row float4s: 120000.
__global__ void k_scale(const float4* __restrict__ in, float4* __restrict__ out, int total4) {
    int i = blockIdx.x * blockDim.x + threadIdx.x;
    if (i >= total4) return;
    int n4 = i % (TLEN / 4);            // position within a batch row
    float4 x = in[i];
    float4 w = ((const float4*)g_w)[n4]; // 1.92MB table, L2-resident across rows
    x.x *= w.x; x.y *= w.y; x.z *= w.z; x.w *= w.w;
    out[i] = x;
}

extern "C" void kernel_launch(void* const* d_in, const int* in_sizes, int n_in,
                              void* d_out, int out_size) {
    const float4* in  = (const float4*)d_in[0];
    float4*       out = (float4*)d_out;

    // Recompute tables every call: deterministic + graph-capturable.
    k_win  <<<(NFFT + 255) / 256, 256>>>();
    k_wfull<<<(TLEN + 255) / 256, 256>>>();

    int total4 = NBATCH * TLEN / 4;     // 3,840,000 — exactly 15000 blocks of 256
    k_scale<<<(total4 + 255) / 256, 256>>>(in, out, total4);
}

// round 3
// speedup vs baseline: 1.1335x; 1.1335x over previous
#include <cuda_runtime.h>

// ---------------------------------------------------------------------------
// CustomSTFT collapses algebraically:
//   mag/phase roundtrip == identity  (rr=sr, ri=si)
//   iDFT(DFT(win*frame)) == (400/401) * win*frame   (exact real-DFT pair;
//     sum_f c_f cos(2*pi*f*d/800) = 400*[d==0] with c_0=c_400=0.5)
//   overlap-add  =>  out[b,n] = x[b,n] * W[n]
// W[n] is periodic with period 200 except in the first/last 200 samples
// (one frame missing at each end). So the whole weight vector is a 600-float
// table: [head 200][interior 200][tail 200].
// ---------------------------------------------------------------------------

#define NFFT   800
#define HOP    200
#define TLEN   480000
#define NBATCH 32
#define ROW4   (TLEN / 4)     // 120000 float4 per row
#define TOTAL4 (NBATCH * ROW4)

__device__ float g_tab[600];  // 3 segments x 200, float4-aligned

// Single-block setup: hann window (double, bit-matches np.hanning->f32),
// then the 3x200 overlap-add weight table.
__global__ void k_setup() {
    __shared__ float win[NFFT];
    int t = threadIdx.x;
    if (t < NFFT) {
        double v = 0.5 - 0.5 * cos(2.0 * 3.14159265358979323846 * (double)t / 799.0);
        win[t] = (float)v;
    }
    __syncthreads();
    if (t < 600) {
        int seg = t / HOP;
        int r   = t % HOP;
        double s;
        if (seg == 0)        // n in [0,200): frames j=0..2 (j=3 would be t=-1)
            s = (double)win[r] + (double)win[r + 200] + (double)win[r + 400];
        else if (seg == 1)   // interior: all 4 overlapping frames
            s = (double)win[r] + (double)win[r + 200] + (double)win[r + 400] + (double)win[r + 600];
        else                 // n in [479800,480000): frames j=1..3 (j=0 would be t=2401)
            s = (double)win[r + 200] + (double)win[r + 400] + (double)win[r + 600];
        g_tab[t] = (float)(s * (400.0 / 401.0));
    }
}

// Streaming multiply. Table is 2.4KB -> L1-resident; indexing is coalesced
// (consecutive threads hit consecutive table float4s). Period 200 and both
// segment boundaries are multiples of 4, so a float4 never straddles them.
__global__ void k_scale(const float4* __restrict__ in, float4* __restrict__ out) {
    int i = blockIdx.x * blockDim.x + threadIdx.x;
    if (i >= TOTAL4) return;
    int n4  = i % ROW4;                       // float4 index within a batch row
    int r4  = n4 % 50;                        // position within the 200-sample period
    int seg = (n4 < 50) ? 0 : ((n4 >= ROW4 - 50) ? 100 : 50);  // float4 offset of segment
    float4 w = __ldg(((const float4*)g_tab) + seg + r4);
    float4 x = in[i];
    x.x *= w.x; x.y *= w.y; x.z *= w.z; x.w *= w.w;
    out[i] = x;
}

extern "C" void kernel_launch(void* const* d_in, const int* in_sizes, int n_in,
                              void* d_out, int out_size) {
    const float4* in  = (const float4*)d_in[0];
    float4*       out = (float4*)d_out;

    // Recompute table every call: deterministic + graph-capturable.
    k_setup<<<1, 1024>>>();

    k_scale<<<(TOTAL4 + 255) / 256, 256>>>(in, out);  // 15000 blocks exactly
}

// round 4
// speedup vs baseline: 1.6209x; 1.4299x over previous
#include <cuda_runtime.h>

// ---------------------------------------------------------------------------
// CustomSTFT collapses algebraically:
//   mag/phase roundtrip == identity  (rr=sr, ri=si)
//   iDFT(DFT(win*frame)) == (400/401) * win*frame   (exact real-DFT pair)
//   overlap-add  =>  out[b,n] = x[b,n] * W[n]
// W[n] is periodic with period 200 except in the first/last 200 samples
// (one overlapping frame missing at each end) -> 600-float table.
// Tolerance budget: reference noise is 2.5e-5 rel; float sinf adds ~1e-7,
// so no double precision needed anywhere (the R3 k_setup double-cos cost
// ~12us of serialized FP64 on one SM).
// ---------------------------------------------------------------------------

#define NFFT   800
#define HOP    200
#define TLEN   480000
#define NBATCH 32
#define ROW4   (TLEN / 4)       // 120000 float4 per row
#define TOTAL4 (NBATCH * ROW4)  // 3,840,000
#define VPT    4                // float4s per thread
#define TPB    256

__device__ float g_tab[600];    // 3 segments x 200 floats, float4-aligned

// Single-block setup, all-float: hann[w] = sin^2(pi*w/799).
__global__ void k_setup() {
    __shared__ float win[NFFT];
    int t = threadIdx.x;
    if (t < NFFT) {
        float a = (float)((double)t * (3.14159265358979323846 / 799.0));
        float s = sinf(a);
        win[t] = s * s;
    }
    __syncthreads();
    if (t < 600) {
        int seg = t / HOP;
        int r   = t % HOP;
        float s;
        if (seg == 0)        // n in [0,200): frames j=0..2
            s = win[r] + win[r + 200] + win[r + 400];
        else if (seg == 1)   // interior: all 4 overlapping frames
            s = win[r] + win[r + 200] + win[r + 400] + win[r + 600];
        else                 // n in [479800,480000): frames j=1..3
            s = win[r + 200] + win[r + 400] + win[r + 600];
        g_tab[t] = s * (400.0f / 401.0f);
    }
}

// Streaming multiply, 4 front-batched float4 loads per thread (MLP=4).
// Block-stride batching keeps each LDG wave warp-coalesced (512B contiguous).
// TOTAL4 = 3750 blocks * 1024 float4s exactly -> no bounds checks.
__global__ void __launch_bounds__(TPB) k_scale(const float4* __restrict__ in,
                                               float4* __restrict__ out) {
    int base = blockIdx.x * (TPB * VPT) + threadIdx.x;

    float4 x[VPT];
#pragma unroll
    for (int v = 0; v < VPT; v++)
        x[v] = in[base + v * TPB];           // 4 independent loads up front

#pragma unroll
    for (int v = 0; v < VPT; v++) {
        int i   = base + v * TPB;
        int n4  = i % ROW4;                  // float4 index within a batch row
        int r4  = n4 % 50;                   // float4 index within the 200-sample period
        int seg = (n4 < 50) ? 0 : ((n4 >= ROW4 - 50) ? 100 : 50);
        float4 w = __ldg(((const float4*)g_tab) + seg + r4);  // 2.4KB, L1-hit
        x[v].x *= w.x; x[v].y *= w.y; x[v].z *= w.z; x[v].w *= w.w;
        out[i] = x[v];
    }
}

extern "C" void kernel_launch(void* const* d_in, const int* in_sizes, int n_in,
                              void* d_out, int out_size) {
    const float4* in  = (const float4*)d_in[0];
    float4*       out = (float4*)d_out;

    // Recompute table every call: deterministic + graph-capturable.
    k_setup<<<1, 1024>>>();

    k_scale<<<TOTAL4 / (TPB * VPT), TPB>>>(in, out);  // 3750 blocks exactly
}